// round 1
// baseline (speedup 1.0000x reference)
#include <cuda_runtime.h>
#include <cuda_bf16.h>

// Problem shape (fixed by reference setup_inputs)
#define BB 16
#define CC 20
#define HHH 256
#define WWW 256
constexpr int NCH   = BB * CC;          // 320
constexpr int HWC   = HHH * WWW;        // 65536
constexpr long long NTOT = (long long)NCH * HWC;  // 20971520
constexpr int BLOCKS_PER_CH = 4;
constexpr int THREADS = 256;
constexpr int CHUNK = HWC / BLOCKS_PER_CH;        // 16384 elems
constexpr int ITERS = CHUNK / (4 * THREADS);      // 16 float4 per thread

// Scratch: per-channel [Sp, Spy, Spx, Spr2, mass, Sty, Stx] then 3 globals
// [focal_sum, mse_sum, l1_sum]
constexpr int NACC = NCH * 7 + 3;
__device__ float g_acc[NACC];

__global__ void zero_kernel() {
    int i = blockIdx.x * blockDim.x + threadIdx.x;
    if (i < NACC) g_acc[i] = 0.0f;
}

__global__ __launch_bounds__(THREADS) void pass_kernel(
    const float4* __restrict__ pred, const float4* __restrict__ targ)
{
    int blk = blockIdx.x;
    int ch  = blk >> 2;           // / BLOCKS_PER_CH
    int sub = blk & 3;
    int base4 = (ch * HWC + sub * CHUNK) >> 2;

    float focal = 0.f, mse = 0.f, l1 = 0.f;
    float Sp = 0.f, Spy = 0.f, Spx = 0.f, Spr2 = 0.f;
    float mass = 0.f, Sty = 0.f, Stx = 0.f;

#pragma unroll
    for (int it = 0; it < ITERS; ++it) {
        int idx4 = base4 + it * THREADS + threadIdx.x;
        float4 pr = pred[idx4];
        float4 tg = targ[idx4];

        int hw   = (idx4 << 2) & (HWC - 1);
        float y  = (float)(hw >> 8);
        float x0 = (float)(hw & 255);
        float yy = y * y;

#define LANE(PV, TV, XO)                                                    \
        {                                                                   \
            float pv = (PV), tv = (TV);                                     \
            float x  = x0 + (XO);                                           \
            float p  = __fdividef(1.0f, 1.0f + __expf(-pv));                \
            /* pt = t ? p : 1-p  (t is exactly 0 or 1) */                   \
            float pt = fmaf(2.0f * p - 1.0f, tv, 1.0f - p);                 \
            float at = 0.75f - 0.5f * tv;                                   \
            float omp = 1.0f - pt;                                          \
            focal = fmaf(at * omp * omp, -__logf(pt + 1e-8f), focal);       \
            float d = pv - tv;                                              \
            mse = fmaf(d, d, mse);                                          \
            l1 += fabsf(pv);                                                \
            Sp  += p;                                                       \
            Spy = fmaf(p, y, Spy);                                          \
            Spx = fmaf(p, x, Spx);                                          \
            Spr2 = fmaf(p, fmaf(x, x, yy), Spr2);                           \
            mass += tv;                                                     \
            Sty = fmaf(tv, y, Sty);                                         \
            Stx = fmaf(tv, x, Stx);                                         \
        }

        LANE(pr.x, tg.x, 0.0f)
        LANE(pr.y, tg.y, 1.0f)
        LANE(pr.z, tg.z, 2.0f)
        LANE(pr.w, tg.w, 3.0f)
#undef LANE
    }

    // ---- block reduction of 10 values ----
    float vals[10] = {focal, mse, l1, Sp, Spy, Spx, Spr2, mass, Sty, Stx};
#pragma unroll
    for (int v = 0; v < 10; v++) {
#pragma unroll
        for (int o = 16; o > 0; o >>= 1)
            vals[v] += __shfl_xor_sync(0xffffffffu, vals[v], o);
    }

    __shared__ float sred[THREADS / 32][10];
    int warp = threadIdx.x >> 5;
    int lane = threadIdx.x & 31;
    if (lane == 0) {
#pragma unroll
        for (int v = 0; v < 10; v++) sred[warp][v] = vals[v];
    }
    __syncthreads();

    if (threadIdx.x < 10) {
        float s = 0.f;
#pragma unroll
        for (int w = 0; w < THREADS / 32; w++) s += sred[w][threadIdx.x];
        if (threadIdx.x < 3) {
            // globals: focal, mse, l1
            atomicAdd(&g_acc[NCH * 7 + threadIdx.x], s);
        } else {
            // per-channel: Sp..Stx at ch*7 + (idx-3)
            atomicAdd(&g_acc[ch * 7 + (threadIdx.x - 3)], s);
        }
    }
}

__global__ void final_kernel(float* __restrict__ out, int out_size) {
    // one block of 512 threads; first 320 handle one channel each
    int tid = threadIdx.x;
    float conc = 0.f;
    float nv = 0.f;
    if (tid < NCH) {
        const float* a = &g_acc[tid * 7];
        float Sp = a[0], Spy = a[1], Spx = a[2], Spr2 = a[3];
        float mass = a[4], Sty = a[5], Stx = a[6];
        bool valid = mass > 0.0f;
        float safe = valid ? mass : 1.0f;
        float cy = Sty / safe;
        float cx = Stx / safe;
        float ps = (Spr2 - 2.0f * (cy * Spy + cx * Spx)
                    + (cy * cy + cx * cx) * Sp) * (1.0f / (float)HWC);
        if (valid) { conc = ps; nv = 1.0f; }
    }
#pragma unroll
    for (int o = 16; o > 0; o >>= 1) {
        conc += __shfl_xor_sync(0xffffffffu, conc, o);
        nv   += __shfl_xor_sync(0xffffffffu, nv, o);
    }
    __shared__ float sc[16], sn[16];
    int warp = tid >> 5, lane = tid & 31;
    if (lane == 0) { sc[warp] = conc; sn[warp] = nv; }
    __syncthreads();
    if (tid == 0) {
        float ct = 0.f, nt = 0.f;
#pragma unroll
        for (int w = 0; w < 16; w++) { ct += sc[w]; nt += sn[w]; }

        float inv = 1.0f / (float)NTOT;
        float focal    = g_acc[NCH * 7 + 0] * inv;
        float sparsity = g_acc[NCH * 7 + 1] * inv + 1.0f * (g_acc[NCH * 7 + 2] * inv);
        float concentration = (nt > 0.f) ? (ct / nt) : 0.0f;  // CONC_INNER_W = 1
        float total = 1.0f * focal + 0.8f * sparsity + 1.5f * concentration;

        out[0] = total;
        if (out_size > 1) out[1] = focal;
        if (out_size > 2) out[2] = sparsity;
        if (out_size > 3) out[3] = concentration;
    }
}

extern "C" void kernel_launch(void* const* d_in, const int* in_sizes, int n_in,
                              void* d_out, int out_size) {
    const float4* pred = (const float4*)d_in[0];
    const float4* targ = (const float4*)d_in[1];
    float* out = (float*)d_out;

    zero_kernel<<<(NACC + 255) / 256, 256>>>();
    pass_kernel<<<NCH * BLOCKS_PER_CH, THREADS>>>(pred, targ);
    final_kernel<<<1, 512>>>(out, out_size);
}